// round 1
// baseline (speedup 1.0000x reference)
#include <cuda_runtime.h>
#include <math.h>

#define NBLK 64
#define NTHR 256
#define WID  1024
#define HID  256
#define NST  17
#define XD   273
#define TLEN 64
#define SUB  8

// ---------------- global communication buffers ----------------
__device__ __align__(128) float g_z[2][WID];
__device__ __align__(128) float g_dh[HID];
__device__ __align__(128) unsigned g_count;   // zero at every kernel exit
__device__ __align__(128) unsigned g_gen;     // monotonic across graph replays

__device__ __forceinline__ void grid_barrier()
{
    __syncthreads();
    if (threadIdx.x == 0) {
        __threadfence();
        unsigned gen = *(volatile unsigned*)&g_gen;
        unsigned t = atomicAdd(&g_count, 1u);
        if (t == (unsigned)(NBLK - 1)) {
            *(volatile unsigned*)&g_count = 0u;
            __threadfence();
            atomicAdd(&g_gen, 1u);
        } else {
            while (*(volatile unsigned*)&g_gen == gen) { }
        }
        __threadfence();
    }
    __syncthreads();
}

__device__ __forceinline__ float red16(float v)
{
    v += __shfl_xor_sync(0xffffffffu, v, 8);
    v += __shfl_xor_sync(0xffffffffu, v, 4);
    v += __shfl_xor_sync(0xffffffffu, v, 2);
    v += __shfl_xor_sync(0xffffffffu, v, 1);
    return v;
}

__device__ __forceinline__ float softplus_f(float x)
{
    // log1p(exp(x)) stable form: max(x,0) + log1p(exp(-|x|))
    return fmaxf(x, 0.0f) + log1pf(expf(-fabsf(x)));
}

// One RHS evaluation. On entry: s_stage[0..272] valid in every CTA (synced).
// On exit: s_kst[0..16] holds dstate, s_dh[0..255] holds tanh-MLP output
// (un-scaled). Caller must __syncthreads() before consuming.
__device__ void rhs_eval(
    const float* __restrict__ W0, const float* __restrict__ b0,
    const float* __restrict__ Wh, const float* __restrict__ bh,
    const float* __restrict__ Wl, const float* __restrict__ bl,
    const float* __restrict__ beta_W, const float* __restrict__ beta_b,
    float* s_stage, float* s_x, float* s_z, float* s_dh,
    float* s_kst, float* s_red, int rbh, int rbl)
{
    const int tid = threadIdx.x;

    // ----- build x = concat(h, state) -----
    for (int i = tid; i < HID; i += NTHR) s_x[i] = s_stage[NST + i];
    if (tid < NST) s_x[HID + tid] = s_stage[tid];
    __syncthreads();

    // ----- warp 0: bb1 + state derivative (redundant per CTA) -----
    if (tid < 32) {
        float a = 0.0f;
        #pragma unroll
        for (int m = 0; m < 8; m++)
            a = fmaf(beta_W[tid + 32 * m], s_stage[NST + tid + 32 * m], a);
        #pragma unroll
        for (int o = 16; o; o >>= 1) a += __shfl_xor_sync(0xffffffffu, a, o);
        if (tid == 0) {
            const float xi = (float)(13.0 / 12.0);
            const float mu = (float)(0.041 / 12.0);
            const float sg = (float)(91.0 / 12.0);
            const float nu = (float)(36.0 / 12.0);
            const float ga = (float)(1.8 / 12.0);
            float bb1 = 8.0f * (1.0f / (1.0f + expf(-(a + beta_b[0])))) + 25.0f;
            float bb2 = 0.5f * bb1, bb3 = 0.35f * bb1, bb4 = 0.25f * bb1;
            float M  = s_stage[0],  S1 = s_stage[1],  E1 = s_stage[2];
            float E2 = s_stage[3],  E3 = s_stage[4],  E4 = s_stage[5];
            float I1 = s_stage[6],  I2 = s_stage[7],  I3 = s_stage[8], I4 = s_stage[9];
            float R1 = s_stage[10], R2 = s_stage[11], R3 = s_stage[12], R4 = s_stage[13];
            float S2 = s_stage[14], S3 = s_stage[15], S4 = s_stage[16];
            float I = I1 + I2 + I3 + I4;
            float R = R1 + R2 + R3 + R4;
            s_kst[0]  = R * mu - (xi + mu) * M;
            s_kst[1]  = mu * (1.0f - R) + xi * M - mu * S1 - bb1 * I * S1;
            s_kst[2]  = bb1 * I * S1 - (mu + sg) * E1;
            s_kst[3]  = bb2 * I * S2 - (mu + sg) * E2;
            s_kst[4]  = bb3 * I * S3 - (mu + sg) * E3;
            s_kst[5]  = bb4 * I * S4 - (mu + sg) * E4;
            s_kst[6]  = sg * E1 - (nu + mu) * I1;
            s_kst[7]  = sg * E2 - (nu + mu) * I2;
            s_kst[8]  = sg * E3 - (nu + mu) * I3;
            s_kst[9]  = sg * E4 - (nu + mu) * I4;
            s_kst[10] = nu * I1 - (mu + ga) * R1;
            s_kst[11] = nu * I2 - (mu + ga) * R2;
            s_kst[12] = nu * I3 - (mu + ga) * R3;
            s_kst[13] = nu * I4 - (mu + ga) * R4;
            s_kst[14] = ga * R1 - mu * S2 - bb2 * I * S2;
            s_kst[15] = ga * R2 - mu * S3 - bb3 * I * S3;
            s_kst[16] = ga * (R3 + R4) - mu * S4 - bb4 * I * S4;
        }
    }

    // ----- layer 0: W0 (1024 x 273), 16 rows/CTA, 16 threads/row -----
    {
        int r = rbh + (tid >> 4);
        int s = tid & 15;
        const float* wrow = W0 + (size_t)r * XD;
        float a0 = 0.0f, a1 = 0.0f;
        #pragma unroll
        for (int j = 0; j < 18; j += 2) {
            int c0 = s + (j << 4);
            int c1 = s + ((j + 1) << 4);
            if (c0 < XD) a0 = fmaf(wrow[c0], s_x[c0], a0);
            if (c1 < XD) a1 = fmaf(wrow[c1], s_x[c1], a1);
        }
        float a = red16(a0 + a1);
        if (s == 0) g_z[0][r] = softplus_f(a + b0[r]);
    }
    grid_barrier();

    // ----- hidden layers: Wh[l] (1024 x 1024) -----
    int buf = 0;
    #pragma unroll 1
    for (int l = 0; l < 3; l++) {
        ((float4*)s_z)[tid] = __ldcg(((const float4*)g_z[buf]) + tid);
        __syncthreads();
        int r = rbh + (tid >> 4);
        int s = tid & 15;
        const float* wrow = Wh + ((size_t)l << 20) + ((size_t)r << 10);
        float ax = 0.0f, ay = 0.0f, az = 0.0f, aw = 0.0f;
        #pragma unroll
        for (int j = 0; j < 16; j++) {
            float4 w  = *(const float4*)(wrow + (s << 2) + (j << 6));
            float4 z4 = *(const float4*)(s_z  + (s << 2) + (j << 6));
            ax = fmaf(w.x, z4.x, ax);
            ay = fmaf(w.y, z4.y, ay);
            az = fmaf(w.z, z4.z, az);
            aw = fmaf(w.w, z4.w, aw);
        }
        float a = red16((ax + az) + (ay + aw));
        if (s == 0) g_z[buf ^ 1][r] = softplus_f(a + bh[(l << 10) + r]);
        grid_barrier();
        buf ^= 1;
    }

    // ----- output layer: Wl (256 x 1024), 4 rows/CTA, 64 threads/row -----
    ((float4*)s_z)[tid] = __ldcg(((const float4*)g_z[buf]) + tid);
    __syncthreads();
    {
        int g = tid & 63;
        int r = tid >> 6;                 // local row 0..3
        const float* wrow = Wl + (size_t)(rbl + r) * WID;
        float ax = 0.0f, ay = 0.0f, az = 0.0f, aw = 0.0f;
        #pragma unroll
        for (int j = 0; j < 4; j++) {
            float4 w  = *(const float4*)(wrow + (g << 2) + (j << 8));
            float4 z4 = *(const float4*)(s_z  + (g << 2) + (j << 8));
            ax = fmaf(w.x, z4.x, ax);
            ay = fmaf(w.y, z4.y, ay);
            az = fmaf(w.z, z4.z, az);
            aw = fmaf(w.w, z4.w, aw);
        }
        float a = (ax + az) + (ay + aw);
        #pragma unroll
        for (int o = 16; o; o >>= 1) a += __shfl_xor_sync(0xffffffffu, a, o);
        if ((tid & 31) == 0) s_red[tid >> 5] = a;
    }
    __syncthreads();
    if (tid < 4) {
        float a = s_red[2 * tid] + s_red[2 * tid + 1];
        float u = 0.01f * (a + bl[rbl + tid]);
        g_dh[rbl + tid] = tanhf(u);
    }
    grid_barrier();

    // pull full dh into local smem (one element per thread)
    s_dh[tid] = __ldcg(&g_dh[tid]);
}

__global__ void __launch_bounds__(NTHR)
ode_kernel(const float* __restrict__ ts,
           const float* __restrict__ W0, const float* __restrict__ b0,
           const float* __restrict__ Wh, const float* __restrict__ bh,
           const float* __restrict__ Wl, const float* __restrict__ bl,
           const float* __restrict__ beta_W, const float* __restrict__ beta_b,
           const float* __restrict__ hvec, const float* __restrict__ scale,
           const float* __restrict__ y0_log, float* __restrict__ out)
{
    __shared__ float s_y[XD], s_stage[XD], s_kacc[XD];
    __shared__ __align__(16) float s_x[XD + 15];
    __shared__ __align__(16) float s_z[WID];
    __shared__ float s_dh[HID], s_kst[NST], s_red[8];

    const int tid = threadIdx.x;
    const int cta = blockIdx.x;
    const int rbh = cta << 4;   // 16 rows/CTA for 1024-wide layers
    const int rbl = cta << 2;   // 4 rows/CTA for the 256-wide output layer
    const float sc = scale[0];

    // y0 = concat(softmax(y0_log), hvec)
    if (tid == 0) {
        float e[NST];
        float m = -1e30f;
        for (int i = 0; i < NST; i++) { e[i] = y0_log[i]; if (e[i] > m) m = e[i]; }
        float ssum = 0.0f;
        for (int i = 0; i < NST; i++) { e[i] = expf(e[i] - m); ssum += e[i]; }
        for (int i = 0; i < NST; i++) s_y[i] = e[i] / ssum;
    }
    for (int i = tid; i < HID; i += NTHR) s_y[NST + i] = hvec[i];
    __syncthreads();

    // output row 0
    if (cta == 0) {
        if (tid < NST) out[tid] = s_y[tid];
        for (int i = tid; i < HID; i += NTHR) out[TLEN * NST + i] = s_y[NST + i];
    }

    for (int iv = 0; iv < TLEN - 1; iv++) {
        float dt = (ts[iv + 1] - ts[iv]) / (float)SUB;
        for (int ss = 0; ss < SUB; ss++) {
            for (int i = tid; i < XD; i += NTHR) { s_stage[i] = s_y[i]; s_kacc[i] = 0.0f; }
            __syncthreads();
            #pragma unroll 1
            for (int st = 0; st < 4; st++) {
                rhs_eval(W0, b0, Wh, bh, Wl, bl, beta_W, beta_b,
                         s_stage, s_x, s_z, s_dh, s_kst, s_red, rbh, rbl);
                __syncthreads();
                float w = (st == 0 || st == 3) ? 1.0f : 2.0f;
                float c = (st < 2) ? 0.5f * dt : dt;
                for (int i = tid; i < XD; i += NTHR) {
                    float k = (i < NST) ? s_kst[i] : sc * s_dh[i - NST];
                    s_kacc[i] += w * k;
                    if (st < 3) s_stage[i] = fmaf(c, k, s_y[i]);
                }
                __syncthreads();
            }
            for (int i = tid; i < XD; i += NTHR)
                s_y[i] = fmaf(dt / 6.0f, s_kacc[i], s_y[i]);
            __syncthreads();
        }
        if (cta == 0) {
            if (tid < NST) out[(iv + 1) * NST + tid] = s_y[tid];
            for (int i = tid; i < HID; i += NTHR)
                out[TLEN * NST + (iv + 1) * HID + i] = s_y[NST + i];
        }
    }
}

extern "C" void kernel_launch(void* const* d_in, const int* in_sizes, int n_in,
                              void* d_out, int out_size)
{
    (void)in_sizes; (void)n_in; (void)out_size;
    ode_kernel<<<NBLK, NTHR>>>(
        (const float*)d_in[0],   // ts
        (const float*)d_in[1],   // W0
        (const float*)d_in[2],   // b0
        (const float*)d_in[3],   // Wh
        (const float*)d_in[4],   // bh
        (const float*)d_in[5],   // Wl
        (const float*)d_in[6],   // bl
        (const float*)d_in[7],   // beta_W
        (const float*)d_in[8],   // beta_b
        (const float*)d_in[9],   // hvec
        (const float*)d_in[10],  // scale
        (const float*)d_in[11],  // y0_log
        (float*)d_out);
}